// round 15
// baseline (speedup 1.0000x reference)
#include <cuda_runtime.h>
#include <cuda_fp16.h>
#include <math.h>
#include <stdint.h>

#define T_TOK 4096
#define DIM   1024
#define NE    8
#define FF    4096
#define NPAIR (2*T_TOK)
#define CAPP  9216             // 8192 + 8*128 padding (segments 128-aligned)

// ---------------- scratch (device globals) ----------------------------------
__device__ __half g_Hh[(size_t)CAPP * FF];
__device__ __half g_xh[(size_t)T_TOK * DIM];
__device__ float g_gwc[DIM * NE];          // gate_w + noise_w combined
__device__ int   g_pair_tok[CAPP];
__device__ float g_pair_sc[CAPP];
__device__ int   g_tok_e[NPAIR];
__device__ float g_tok_p[NPAIR];
__device__ int   g_counts[NE];
__device__ int   g_cursor[NE];
__device__ double g_impd[NE];              // summed routing probs (double)

// ---------------- helpers ----------------------------------------------------
__device__ __forceinline__ uint32_t smem_u32(const void* p) {
    return (uint32_t)__cvta_generic_to_shared(p);
}
__device__ __forceinline__ uint32_t pack_h2(float a, float b) {
    __half2 h = __floats2half2_rn(a, b);
    return *(uint32_t*)&h;
}
__device__ __forceinline__ float4 ldg_cg4(const float* p) {   // L1-bypass load
    float4 v;
    asm volatile("ld.global.cg.v4.f32 {%0,%1,%2,%3}, [%4];"
                 : "=f"(v.x), "=f"(v.y), "=f"(v.z), "=f"(v.w) : "l"(p));
    return v;
}
__device__ __forceinline__ void mma_f16(float& c0, float& c1, float& c2, float& c3,
                                        uint32_t a0, uint32_t a1, uint32_t a2, uint32_t a3,
                                        uint32_t b0, uint32_t b1) {
    asm volatile(
        "mma.sync.aligned.m16n8k16.row.col.f32.f16.f16.f32 "
        "{%0,%1,%2,%3}, {%4,%5,%6,%7}, {%8,%9}, {%0,%1,%2,%3};"
        : "+f"(c0), "+f"(c1), "+f"(c2), "+f"(c3)
        : "r"(a0), "r"(a1), "r"(a2), "r"(a3), "r"(b0), "r"(b1));
}
__device__ __forceinline__ void ldsm_x4(uint32_t& r0, uint32_t& r1, uint32_t& r2,
                                        uint32_t& r3, uint32_t addr) {
    asm volatile("ldmatrix.sync.aligned.m8n8.x4.shared.b16 {%0,%1,%2,%3}, [%4];"
                 : "=r"(r0), "=r"(r1), "=r"(r2), "=r"(r3) : "r"(addr));
}
__device__ __forceinline__ void ldsm_x4t(uint32_t& r0, uint32_t& r1, uint32_t& r2,
                                         uint32_t& r3, uint32_t addr) {
    asm volatile("ldmatrix.sync.aligned.m8n8.x4.trans.shared.b16 {%0,%1,%2,%3}, [%4];"
                 : "=r"(r0), "=r"(r1), "=r"(r2), "=r"(r3) : "r"(addr));
}
__device__ __forceinline__ void cpa16(uint32_t dst, const void* src) {
    asm volatile("cp.async.cg.shared.global [%0], [%1], 16;"
                 :: "r"(dst), "l"(src));
}
#define CP_COMMIT() asm volatile("cp.async.commit_group;" ::: "memory")
#define CP_WAIT2()  asm volatile("cp.async.wait_group 2;"  ::: "memory")

// ---------------- setup kernel ------------------------------------------------
__global__ void k_setup(float4* out, const float* __restrict__ gw,
                        const float* __restrict__ nw) {
    int i = blockIdx.x * blockDim.x + threadIdx.x;
    if (i < T_TOK * DIM / 4) out[i] = make_float4(0.f, 0.f, 0.f, 0.f);
    if (i < CAPP) { g_pair_tok[i] = -1; g_pair_sc[i] = 0.f; }
    if (i < DIM * NE) g_gwc[i] = gw[i] + nw[i];
    if (i < NE) { g_counts[i] = 0; g_cursor[i] = 0; g_impd[i] = 0.0; }
}

// ---------------- router: 8 tokens / 256-thread block ------------------------
__global__ void __launch_bounds__(256) k_router(
    const float* __restrict__ x, const float* __restrict__ noise,
    const float* __restrict__ gb, const float* __restrict__ nb)
{
    __shared__ float sx[8 * DIM];   // 32 KB
    __shared__ float sl[64];
    __shared__ double simp[NE];
    const int tid = threadIdx.x;
    const int t0 = blockIdx.x * 8;

    if (tid < NE) simp[tid] = 0.0;
    for (int i = tid; i < 8 * DIM / 4; i += 256) {
        float4 v = ((const float4*)(x + (size_t)t0 * DIM))[i];
        *(float4*)&sx[i * 4] = v;
    }
    __syncthreads();
    for (int i = tid; i < 8 * DIM / 2; i += 256) {
        *(uint32_t*)&g_xh[(size_t)t0 * DIM + 2 * i] = pack_h2(sx[2 * i], sx[2 * i + 1]);
    }
    const int p = tid >> 2;
    const int q = tid & 3;
    const int tok = p >> 3, e = p & 7;
    const float* xr = &sx[tok * DIM];
    float s = 0.f;
    #pragma unroll 4
    for (int k = q; k < DIM; k += 4)
        s += xr[k] * g_gwc[k * NE + e];
    s += __shfl_down_sync(0xffffffffu, s, 1);
    s += __shfl_down_sync(0xffffffffu, s, 2);
    if (q == 0) sl[p] = s;
    __syncthreads();

    if (tid < 8) {
        int t = t0 + tid;
        float lg[NE];
        #pragma unroll
        for (int k = 0; k < NE; k++)
            lg[k] = sl[tid * NE + k] + gb[k] + nb[k] + noise[t * NE + k];
        float v0 = -1e30f; int i0 = 0;
        #pragma unroll
        for (int k = 0; k < NE; k++) { if (lg[k] > v0) { v0 = lg[k]; i0 = k; } }
        float v1 = -1e30f; int i1 = 0;
        #pragma unroll
        for (int k = 0; k < NE; k++) { if (k == i0) continue; if (lg[k] > v1) { v1 = lg[k]; i1 = k; } }
        float e1 = expf(v1 - v0);
        float z = 1.f + e1;
        float p0 = 1.f / z, p1 = e1 / z;
        g_tok_e[2 * t] = i0;  g_tok_e[2 * t + 1] = i1;
        g_tok_p[2 * t] = p0;  g_tok_p[2 * t + 1] = p1;
        atomicAdd(&g_counts[i0], 1);
        atomicAdd(&g_counts[i1], 1);
        atomicAdd(&simp[i0], (double)p0);
        atomicAdd(&simp[i1], (double)p1);
    }
    __syncthreads();
    if (tid < NE && simp[tid] != 0.0) atomicAdd(&g_impd[tid], simp[tid]);
}

// ---------------- inline segment offsets --------------------------------------
__device__ __forceinline__ int seg_start(int e) {
    int acc = 0;
    #pragma unroll
    for (int i = 0; i < NE; i++)
        if (i < e) acc += ((g_counts[i] + 127) >> 7) << 7;
    return acc;
}
__device__ __forceinline__ int tile_expert(int row0) {
    int acc = 0, e = -1;
    #pragma unroll
    for (int i = 0; i < NE; i++) {
        int pad = ((g_counts[i] + 127) >> 7) << 7;
        if (row0 >= acc && row0 < acc + pad) e = i;
        acc += pad;
    }
    return e;
}

__global__ void k_scatter() {
    int i = blockIdx.x * blockDim.x + threadIdx.x;
    if (i >= NPAIR) return;
    int t = i >> 1;
    int e = g_tok_e[i];
    float p = g_tok_p[i];
    int pos = seg_start(e) + atomicAdd(&g_cursor[e], 1);
    g_pair_tok[pos] = t;
    g_pair_sc[pos]  = p;
}

// ---------------- SMEM geometry (halfs) --------------------------------------
#define AST 40
#define BST 136
#define A_STAGE_H (128 * AST)
#define B_STAGE_H (32 * BST)
#define NSTAGE 4
#define GEMM_SMEM ((A_STAGE_H + B_STAGE_H) * NSTAGE * 2)   // 75776 B

// =============================================================================
// fp16 mma.sync GEMM, 128x128 CTA tile, 8 warps, K-tile 32 (R13/R14-proven).
// A: fp16 via 4-stage cp.async (L1-bypass).  B: fp32 ld.global.cg -> fp16
// inline, register-staged.
// =============================================================================

__global__ void __launch_bounds__(256, 2) k_mma_gemm1(
    const float* __restrict__ w1, const float* __restrict__ b1)
{
    extern __shared__ __half sm[];
    __half* As = sm;
    __half* Bs = sm + NSTAGE * A_STAGE_H;
    __shared__ int stok[128];

    const int tid = threadIdx.x;
    const int n0 = blockIdx.x * 128;
    const int row0 = blockIdx.y * 128;
    const int e = tile_expert(row0);
    if (e < 0) return;
    const float* __restrict__ w = w1 + (size_t)e * DIM * FF;

    if (tid < 128) stok[tid] = g_pair_tok[row0 + tid];
    __syncthreads();

    const int lane = tid & 31;
    const int wrp = tid >> 5;
    const int wm = (wrp & 1) * 64;
    const int wn = (wrp >> 1) * 32;
    const int qr = lane >> 2;
    const uint32_t as_base = smem_u32(As);

    const int ar = tid >> 2;
    const int ac8 = (tid & 3) * 8;
    int ta0 = stok[ar];      if (ta0 < 0) ta0 = 0;
    int ta1 = stok[ar + 64]; if (ta1 < 0) ta1 = 0;
    const __half* xr0 = g_xh + (size_t)ta0 * DIM + ac8;
    const __half* xr1 = g_xh + (size_t)ta1 * DIM + ac8;
    const uint32_t a_d0 = as_base + (ar * AST + ac8) * 2;
    const uint32_t a_d1 = as_base + ((ar + 64) * AST + ac8) * 2;

    const int br = tid >> 4;
    const int bc8 = (tid & 15) * 8;
    const float* wr32 = w + n0 + bc8;

    const int a_r = (lane & 15);
    const int a_k = (lane & 16) >> 1;
    const int b_k = (lane & 7) + ((lane & 8) ? 8 : 0);
    const int b_n = (lane & 16) >> 1;
    const uint32_t bs_base = smem_u32(Bs);

    float acc[4][4][4];
    #pragma unroll
    for (int i = 0; i < 4; i++)
        #pragma unroll
        for (int j = 0; j < 4; j++)
            #pragma unroll
            for (int q = 0; q < 4; q++) acc[i][j][q] = 0.f;

    const int NK = DIM / 32;
    #pragma unroll
    for (int s = 0; s < NSTAGE - 1; ++s) {
        int kt = s * 32;
        uint32_t ao = s * A_STAGE_H * 2;
        cpa16(a_d0 + ao, xr0 + kt);
        cpa16(a_d1 + ao, xr1 + kt);
        CP_COMMIT();
    }
    float4 b0a = ldg_cg4(wr32 + (size_t)br * FF);
    float4 b0b = ldg_cg4(wr32 + (size_t)br * FF + 4);
    float4 b1a = ldg_cg4(wr32 + (size_t)(br + 16) * FF);
    float4 b1b = ldg_cg4(wr32 + (size_t)(br + 16) * FF + 4);

    for (int ki = 0; ki < NK; ++ki) {
        const int s = ki % NSTAGE;
        *(uint4*)&Bs[s * B_STAGE_H + br * BST + bc8] =
            make_uint4(pack_h2(b0a.x, b0a.y), pack_h2(b0a.z, b0a.w),
                       pack_h2(b0b.x, b0b.y), pack_h2(b0b.z, b0b.w));
        *(uint4*)&Bs[s * B_STAGE_H + (br + 16) * BST + bc8] =
            make_uint4(pack_h2(b1a.x, b1a.y), pack_h2(b1a.z, b1a.w),
                       pack_h2(b1b.x, b1b.y), pack_h2(b1b.z, b1b.w));
        if (ki + 1 < NK) {
            int kt = (ki + 1) * 32;
            b0a = ldg_cg4(wr32 + (size_t)(kt + br) * FF);
            b0b = ldg_cg4(wr32 + (size_t)(kt + br) * FF + 4);
            b1a = ldg_cg4(wr32 + (size_t)(kt + br + 16) * FF);
            b1b = ldg_cg4(wr32 + (size_t)(kt + br + 16) * FF + 4);
        }
        CP_WAIT2();
        __syncthreads();
        int kf = ki + NSTAGE - 1;
        if (kf < NK) {
            int kt = kf * 32;
            uint32_t ao = (kf % NSTAGE) * A_STAGE_H * 2;
            cpa16(a_d0 + ao, xr0 + kt);
            cpa16(a_d1 + ao, xr1 + kt);
        }
        CP_COMMIT();

        const uint32_t asb = as_base + s * A_STAGE_H * 2;
        const uint32_t bsb = bs_base + s * B_STAGE_H * 2;
        #pragma unroll
        for (int ks = 0; ks < 2; ++ks) {
            const int k0 = ks * 16;
            uint32_t af[4][4];
            #pragma unroll
            for (int i = 0; i < 4; ++i) {
                uint32_t ad = asb + ((wm + i * 16 + a_r) * AST + k0 + a_k) * 2;
                ldsm_x4(af[i][0], af[i][1], af[i][2], af[i][3], ad);
            }
            uint32_t bf[4][2];
            #pragma unroll
            for (int jp = 0; jp < 2; ++jp) {
                uint32_t bd = bsb + ((k0 + b_k) * BST + wn + jp * 16 + b_n) * 2;
                ldsm_x4t(bf[jp * 2][0], bf[jp * 2][1],
                         bf[jp * 2 + 1][0], bf[jp * 2 + 1][1], bd);
            }
            #pragma unroll
            for (int i = 0; i < 4; ++i)
                #pragma unroll
                for (int j = 0; j < 4; ++j)
                    mma_f16(acc[i][j][0], acc[i][j][1], acc[i][j][2], acc[i][j][3],
                            af[i][0], af[i][1], af[i][2], af[i][3],
                            bf[j][0], bf[j][1]);
        }
    }

    const float* bp = b1 + (size_t)e * FF + n0;
    #pragma unroll
    for (int j = 0; j < 4; ++j) {
        int col = wn + j * 8 + (lane & 3) * 2;
        float bb0 = bp[col], bb1 = bp[col + 1];
        #pragma unroll
        for (int i = 0; i < 4; ++i) {
            int r0 = row0 + wm + i * 16 + qr;
            float a0 = acc[i][j][0] + bb0, a1 = acc[i][j][1] + bb1;
            uint32_t p0 = pack_h2(a0 / (1.f + __expf(-a0)), a1 / (1.f + __expf(-a1)));
            *(uint32_t*)&g_Hh[(size_t)r0 * FF + n0 + col] = p0;
            float a2 = acc[i][j][2] + bb0, a3 = acc[i][j][3] + bb1;
            uint32_t p1 = pack_h2(a2 / (1.f + __expf(-a2)), a3 / (1.f + __expf(-a3)));
            *(uint32_t*)&g_Hh[(size_t)(r0 + 8) * FF + n0 + col] = p1;
        }
    }
}

__global__ void __launch_bounds__(256, 2) k_mma_gemm2(
    const float* __restrict__ w2, const float* __restrict__ b2,
    float* __restrict__ out)
{
    extern __shared__ __half sm[];
    __half* As = sm;
    __half* Bs = sm + NSTAGE * A_STAGE_H;
    __shared__ int   stok[128];
    __shared__ float ssc[128];

    const int tid = threadIdx.x;
    const int n0 = blockIdx.x * 128;
    const int row0 = blockIdx.y * 128;
    const int e = tile_expert(row0);
    if (e < 0) return;
    const float* __restrict__ w = w2 + (size_t)e * FF * DIM;

    if (tid < 128) { stok[tid] = g_pair_tok[row0 + tid]; ssc[tid] = g_pair_sc[row0 + tid]; }
    __syncthreads();

    const int lane = tid & 31;
    const int wrp = tid >> 5;
    const int wm = (wrp & 1) * 64;
    const int wn = (wrp >> 1) * 32;
    const int qr = lane >> 2;
    const uint32_t as_base = smem_u32(As);
    const uint32_t bs_base = smem_u32(Bs);

    const int ar = tid >> 2;
    const int ac8 = (tid & 3) * 8;
    const __half* hr0 = g_Hh + (size_t)(row0 + ar) * FF + ac8;
    const __half* hr1 = g_Hh + (size_t)(row0 + ar + 64) * FF + ac8;
    const uint32_t a_d0 = as_base + (ar * AST + ac8) * 2;
    const uint32_t a_d1 = as_base + ((ar + 64) * AST + ac8) * 2;

    const int br = tid >> 4;
    const int bc8 = (tid & 15) * 8;
    const float* wr32 = w + n0 + bc8;

    const int a_r = (lane & 15);
    const int a_k = (lane & 16) >> 1;
    const int b_k = (lane & 7) + ((lane & 8) ? 8 : 0);
    const int b_n = (lane & 16) >> 1;

    float acc[4][4][4];
    #pragma unroll
    for (int i = 0; i < 4; i++)
        #pragma unroll
        for (int j = 0; j < 4; j++)
            #pragma unroll
            for (int q = 0; q < 4; q++) acc[i][j][q] = 0.f;

    const int NK = FF / 32;
    #pragma unroll
    for (int s = 0; s < NSTAGE - 1; ++s) {
        int kt = s * 32;
        uint32_t ao = s * A_STAGE_H * 2;
        cpa16(a_d0 + ao, hr0 + kt);
        cpa16(a_d1 + ao, hr1 + kt);
        CP_COMMIT();
    }
    float4 b0a = ldg_cg4(wr32 + (size_t)br * DIM);
    float4 b0b = ldg_cg4(wr32 + (size_t)br * DIM + 4);
    float4 b1a = ldg_cg4(wr32 + (size_t)(br + 16) * DIM);
    float4 b1b = ldg_cg4(wr32 + (size_t)(br + 16) * DIM + 4);

    for (int ki = 0; ki < NK; ++ki) {
        const int s = ki % NSTAGE;
        *(uint4*)&Bs[s * B_STAGE_H + br * BST + bc8] =
            make_uint4(pack_h2(b0a.x, b0a.y), pack_h2(b0a.z, b0a.w),
                       pack_h2(b0b.x, b0b.y), pack_h2(b0b.z, b0b.w));
        *(uint4*)&Bs[s * B_STAGE_H + (br + 16) * BST + bc8] =
            make_uint4(pack_h2(b1a.x, b1a.y), pack_h2(b1a.z, b1a.w),
                       pack_h2(b1b.x, b1b.y), pack_h2(b1b.z, b1b.w));
        if (ki + 1 < NK) {
            int kt = (ki + 1) * 32;
            b0a = ldg_cg4(wr32 + (size_t)(kt + br) * DIM);
            b0b = ldg_cg4(wr32 + (size_t)(kt + br) * DIM + 4);
            b1a = ldg_cg4(wr32 + (size_t)(kt + br + 16) * DIM);
            b1b = ldg_cg4(wr32 + (size_t)(kt + br + 16) * DIM + 4);
        }
        CP_WAIT2();
        __syncthreads();
        int kf = ki + NSTAGE - 1;
        if (kf < NK) {
            int kt = kf * 32;
            uint32_t ao = (kf % NSTAGE) * A_STAGE_H * 2;
            cpa16(a_d0 + ao, hr0 + kt);
            cpa16(a_d1 + ao, hr1 + kt);
        }
        CP_COMMIT();

        const uint32_t asb = as_base + s * A_STAGE_H * 2;
        const uint32_t bsb = bs_base + s * B_STAGE_H * 2;
        #pragma unroll
        for (int ks = 0; ks < 2; ++ks) {
            const int k0 = ks * 16;
            uint32_t af[4][4];
            #pragma unroll
            for (int i = 0; i < 4; ++i) {
                uint32_t ad = asb + ((wm + i * 16 + a_r) * AST + k0 + a_k) * 2;
                ldsm_x4(af[i][0], af[i][1], af[i][2], af[i][3], ad);
            }
            uint32_t bf[4][2];
            #pragma unroll
            for (int jp = 0; jp < 2; ++jp) {
                uint32_t bd = bsb + ((k0 + b_k) * BST + wn + jp * 16 + b_n) * 2;
                ldsm_x4t(bf[jp * 2][0], bf[jp * 2][1],
                         bf[jp * 2 + 1][0], bf[jp * 2 + 1][1], bd);
            }
            #pragma unroll
            for (int i = 0; i < 4; ++i)
                #pragma unroll
                for (int j = 0; j < 4; ++j)
                    mma_f16(acc[i][j][0], acc[i][j][1], acc[i][j][2], acc[i][j][3],
                            af[i][0], af[i][1], af[i][2], af[i][3],
                            bf[j][0], bf[j][1]);
        }
    }

    const float* bp = b2 + (size_t)e * DIM + n0;
    #pragma unroll
    for (int j = 0; j < 4; ++j) {
        int col = wn + j * 8 + (lane & 3) * 2;
        float bb0 = bp[col], bb1 = bp[col + 1];
        #pragma unroll
        for (int i = 0; i < 4; ++i) {
            int m = wm + i * 16 + qr;
            int t0 = stok[m], t1 = stok[m + 8];
            if (t0 >= 0) {
                float s = ssc[m];
                atomicAdd(&out[(size_t)t0 * DIM + n0 + col],     s * (acc[i][j][0] + bb0));
                atomicAdd(&out[(size_t)t0 * DIM + n0 + col + 1], s * (acc[i][j][1] + bb1));
            }
            if (t1 >= 0) {
                float s = ssc[m + 8];
                atomicAdd(&out[(size_t)t1 * DIM + n0 + col],     s * (acc[i][j][2] + bb0));
                atomicAdd(&out[(size_t)t1 * DIM + n0 + col + 1], s * (acc[i][j][3] + bb1));
            }
        }
    }
}

// ---------------- aux loss (tiny: g_impd accumulated by router) ---------------
__global__ void k_aux(float* __restrict__ aux_out) {
    if (threadIdx.x == 0) {
        float aux = 0.f;
        const float u = 1.f / (float)NE;
        const float logu = logf(u);
        #pragma unroll
        for (int e = 0; e < NE; e++)
            aux += u * (logu - logf((float)(g_impd[e] / (double)T_TOK) + 1e-8f));
        aux_out[0] = aux;
    }
}

// ---------------- launch -----------------------------------------------------
extern "C" void kernel_launch(void* const* d_in, const int* in_sizes, int n_in,
                              void* d_out, int out_size) {
    const float* x       = (const float*)d_in[0];
    const float* noise   = (const float*)d_in[1];
    const float* gate_w  = (const float*)d_in[2];
    const float* gate_b  = (const float*)d_in[3];
    const float* noise_w = (const float*)d_in[4];
    const float* noise_b = (const float*)d_in[5];
    const float* w1      = (const float*)d_in[6];
    const float* b1      = (const float*)d_in[7];
    const float* w2      = (const float*)d_in[8];
    const float* b2      = (const float*)d_in[9];
    float* out = (float*)d_out;
    (void)in_sizes; (void)n_in;

    static bool init_done = false;
    if (!init_done) {
        cudaFuncSetAttribute(k_mma_gemm1, cudaFuncAttributeMaxDynamicSharedMemorySize, GEMM_SMEM);
        cudaFuncSetAttribute(k_mma_gemm2, cudaFuncAttributeMaxDynamicSharedMemorySize, GEMM_SMEM);
        init_done = true;
    }

    k_setup<<<(T_TOK * DIM / 4 + 255) / 256, 256>>>((float4*)out, gate_w, noise_w);
    k_router<<<T_TOK / 8, 256>>>(x, noise, gate_b, noise_b);
    k_scatter<<<(NPAIR + 255) / 256, 256>>>();
    k_aux<<<1, 32>>>(out + (out_size - 1));
    k_mma_gemm1<<<dim3(FF / 128, CAPP / 128), 256, GEMM_SMEM>>>(w1, b1);
    k_mma_gemm2<<<dim3(DIM / 128, CAPP / 128), 256, GEMM_SMEM>>>(w2, b2, out);
}

// round 16
// speedup vs baseline: 1.0100x; 1.0100x over previous
#include <cuda_runtime.h>
#include <cuda_fp16.h>
#include <math.h>
#include <stdint.h>

#define T_TOK 4096
#define DIM   1024
#define NE    8
#define FF    4096
#define NPAIR (2*T_TOK)
#define CAPP  9216             // 8192 + 8*128 padding (segments 128-aligned)

// ---------------- scratch (device globals) ----------------------------------
__device__ __half g_Hh[(size_t)CAPP * FF];
__device__ __half g_xh[(size_t)T_TOK * DIM];
__device__ float g_gwc[DIM * NE];          // gate_w + noise_w combined
__device__ int   g_pair_tok[CAPP];
__device__ float g_pair_sc[CAPP];
__device__ int   g_tok_e[NPAIR];
__device__ float g_tok_p[NPAIR];
__device__ int   g_counts[NE];
__device__ int   g_cursor[NE];
__device__ double g_impd[NE];              // summed routing probs (double)

// ---------------- helpers ----------------------------------------------------
__device__ __forceinline__ uint32_t smem_u32(const void* p) {
    return (uint32_t)__cvta_generic_to_shared(p);
}
__device__ __forceinline__ uint32_t pack_h2(float a, float b) {
    __half2 h = __floats2half2_rn(a, b);
    return *(uint32_t*)&h;
}
__device__ __forceinline__ void mma_f16(float& c0, float& c1, float& c2, float& c3,
                                        uint32_t a0, uint32_t a1, uint32_t a2, uint32_t a3,
                                        uint32_t b0, uint32_t b1) {
    asm volatile(
        "mma.sync.aligned.m16n8k16.row.col.f32.f16.f16.f32 "
        "{%0,%1,%2,%3}, {%4,%5,%6,%7}, {%8,%9}, {%0,%1,%2,%3};"
        : "+f"(c0), "+f"(c1), "+f"(c2), "+f"(c3)
        : "r"(a0), "r"(a1), "r"(a2), "r"(a3), "r"(b0), "r"(b1));
}
__device__ __forceinline__ void ldsm_x4(uint32_t& r0, uint32_t& r1, uint32_t& r2,
                                        uint32_t& r3, uint32_t addr) {
    asm volatile("ldmatrix.sync.aligned.m8n8.x4.shared.b16 {%0,%1,%2,%3}, [%4];"
                 : "=r"(r0), "=r"(r1), "=r"(r2), "=r"(r3) : "r"(addr));
}
__device__ __forceinline__ void ldsm_x4t(uint32_t& r0, uint32_t& r1, uint32_t& r2,
                                         uint32_t& r3, uint32_t addr) {
    asm volatile("ldmatrix.sync.aligned.m8n8.x4.trans.shared.b16 {%0,%1,%2,%3}, [%4];"
                 : "=r"(r0), "=r"(r1), "=r"(r2), "=r"(r3) : "r"(addr));
}
__device__ __forceinline__ void cpa16(uint32_t dst, const void* src) {
    asm volatile("cp.async.cg.shared.global [%0], [%1], 16;"
                 :: "r"(dst), "l"(src));
}
#define CP_COMMIT() asm volatile("cp.async.commit_group;" ::: "memory")
#define CP_WAIT2()  asm volatile("cp.async.wait_group 2;"  ::: "memory")

// ---------------- setup kernel ------------------------------------------------
__global__ void k_setup(float4* out, const float* __restrict__ gw,
                        const float* __restrict__ nw) {
    int i = blockIdx.x * blockDim.x + threadIdx.x;
    if (i < T_TOK * DIM / 4) out[i] = make_float4(0.f, 0.f, 0.f, 0.f);
    if (i < CAPP) { g_pair_tok[i] = -1; g_pair_sc[i] = 0.f; }
    if (i < DIM * NE) g_gwc[i] = gw[i] + nw[i];
    if (i < NE) { g_counts[i] = 0; g_cursor[i] = 0; g_impd[i] = 0.0; }
}

// ---------------- router: 8 tokens / 256-thread block ------------------------
__global__ void __launch_bounds__(256) k_router(
    const float* __restrict__ x, const float* __restrict__ noise,
    const float* __restrict__ gb, const float* __restrict__ nb)
{
    __shared__ float sx[8 * DIM];   // 32 KB
    __shared__ float sl[64];
    __shared__ double simp[NE];
    const int tid = threadIdx.x;
    const int t0 = blockIdx.x * 8;

    if (tid < NE) simp[tid] = 0.0;
    for (int i = tid; i < 8 * DIM / 4; i += 256) {
        float4 v = ((const float4*)(x + (size_t)t0 * DIM))[i];
        *(float4*)&sx[i * 4] = v;
    }
    __syncthreads();
    for (int i = tid; i < 8 * DIM / 2; i += 256) {
        *(uint32_t*)&g_xh[(size_t)t0 * DIM + 2 * i] = pack_h2(sx[2 * i], sx[2 * i + 1]);
    }
    const int p = tid >> 2;
    const int q = tid & 3;
    const int tok = p >> 3, e = p & 7;
    const float* xr = &sx[tok * DIM];
    float s = 0.f;
    #pragma unroll 4
    for (int k = q; k < DIM; k += 4)
        s += xr[k] * g_gwc[k * NE + e];
    s += __shfl_down_sync(0xffffffffu, s, 1);
    s += __shfl_down_sync(0xffffffffu, s, 2);
    if (q == 0) sl[p] = s;
    __syncthreads();

    if (tid < 8) {
        int t = t0 + tid;
        float lg[NE];
        #pragma unroll
        for (int k = 0; k < NE; k++)
            lg[k] = sl[tid * NE + k] + gb[k] + nb[k] + noise[t * NE + k];
        float v0 = -1e30f; int i0 = 0;
        #pragma unroll
        for (int k = 0; k < NE; k++) { if (lg[k] > v0) { v0 = lg[k]; i0 = k; } }
        float v1 = -1e30f; int i1 = 0;
        #pragma unroll
        for (int k = 0; k < NE; k++) { if (k == i0) continue; if (lg[k] > v1) { v1 = lg[k]; i1 = k; } }
        float e1 = expf(v1 - v0);
        float z = 1.f + e1;
        float p0 = 1.f / z, p1 = e1 / z;
        g_tok_e[2 * t] = i0;  g_tok_e[2 * t + 1] = i1;
        g_tok_p[2 * t] = p0;  g_tok_p[2 * t + 1] = p1;
        atomicAdd(&g_counts[i0], 1);
        atomicAdd(&g_counts[i1], 1);
        atomicAdd(&simp[i0], (double)p0);
        atomicAdd(&simp[i1], (double)p1);
    }
    __syncthreads();
    if (tid < NE && simp[tid] != 0.0) atomicAdd(&g_impd[tid], simp[tid]);
}

// ---------------- inline segment offsets --------------------------------------
__device__ __forceinline__ int seg_start(int e) {
    int acc = 0;
    #pragma unroll
    for (int i = 0; i < NE; i++)
        if (i < e) acc += ((g_counts[i] + 127) >> 7) << 7;
    return acc;
}
__device__ __forceinline__ int tile_expert(int row0) {
    int acc = 0, e = -1;
    #pragma unroll
    for (int i = 0; i < NE; i++) {
        int pad = ((g_counts[i] + 127) >> 7) << 7;
        if (row0 >= acc && row0 < acc + pad) e = i;
        acc += pad;
    }
    return e;
}

// scatter + (block 0) aux loss
__global__ void k_scatter(float* __restrict__ aux_out) {
    int i = blockIdx.x * blockDim.x + threadIdx.x;
    if (i == 0) {
        float aux = 0.f;
        const float u = 1.f / (float)NE;
        const float logu = logf(u);
        #pragma unroll
        for (int e = 0; e < NE; e++)
            aux += u * (logu - logf((float)(g_impd[e] / (double)T_TOK) + 1e-8f));
        aux_out[0] = aux;
    }
    if (i >= NPAIR) return;
    int t = i >> 1;
    int e = g_tok_e[i];
    float p = g_tok_p[i];
    int pos = seg_start(e) + atomicAdd(&g_cursor[e], 1);
    g_pair_tok[pos] = t;
    g_pair_sc[pos]  = p;
}

// ---------------- SMEM geometry (halfs) --------------------------------------
#define AST 40
#define BST 136
#define A_STAGE_H (128 * AST)
#define B_STAGE_H (32 * BST)
#define NSTAGE 4
#define GEMM_SMEM ((A_STAGE_H + B_STAGE_H) * NSTAGE * 2)   // 75776 B

// =============================================================================
// fp16 mma.sync GEMM, 128x128 CTA tile, 8 warps, K-tile 32 (measured-best R14).
// A: fp16 via 4-stage cp.async.  B: fp32 LDG -> fp16 inline, register-staged.
// =============================================================================

__global__ void __launch_bounds__(256, 2) k_mma_gemm1(
    const float* __restrict__ w1, const float* __restrict__ b1)
{
    extern __shared__ __half sm[];
    __half* As = sm;
    __half* Bs = sm + NSTAGE * A_STAGE_H;
    __shared__ int stok[128];

    const int tid = threadIdx.x;
    const int n0 = blockIdx.x * 128;
    const int row0 = blockIdx.y * 128;
    const int e = tile_expert(row0);
    if (e < 0) return;
    const float* __restrict__ w = w1 + (size_t)e * DIM * FF;

    if (tid < 128) stok[tid] = g_pair_tok[row0 + tid];
    __syncthreads();

    const int lane = tid & 31;
    const int wrp = tid >> 5;
    const int wm = (wrp & 1) * 64;
    const int wn = (wrp >> 1) * 32;
    const int qr = lane >> 2;
    const uint32_t as_base = smem_u32(As);

    const int ar = tid >> 2;
    const int ac8 = (tid & 3) * 8;
    int ta0 = stok[ar];      if (ta0 < 0) ta0 = 0;
    int ta1 = stok[ar + 64]; if (ta1 < 0) ta1 = 0;
    const __half* xr0 = g_xh + (size_t)ta0 * DIM + ac8;
    const __half* xr1 = g_xh + (size_t)ta1 * DIM + ac8;
    const uint32_t a_d0 = as_base + (ar * AST + ac8) * 2;
    const uint32_t a_d1 = as_base + ((ar + 64) * AST + ac8) * 2;

    const int br = tid >> 4;
    const int bc8 = (tid & 15) * 8;
    const float* wr32 = w + n0 + bc8;

    const int a_r = (lane & 15);
    const int a_k = (lane & 16) >> 1;
    const int b_k = (lane & 7) + ((lane & 8) ? 8 : 0);
    const int b_n = (lane & 16) >> 1;
    const uint32_t bs_base = smem_u32(Bs);

    float acc[4][4][4];
    #pragma unroll
    for (int i = 0; i < 4; i++)
        #pragma unroll
        for (int j = 0; j < 4; j++)
            #pragma unroll
            for (int q = 0; q < 4; q++) acc[i][j][q] = 0.f;

    const int NK = DIM / 32;
    #pragma unroll
    for (int s = 0; s < NSTAGE - 1; ++s) {
        int kt = s * 32;
        uint32_t ao = s * A_STAGE_H * 2;
        cpa16(a_d0 + ao, xr0 + kt);
        cpa16(a_d1 + ao, xr1 + kt);
        CP_COMMIT();
    }
    float4 b0a = *(const float4*)(wr32 + (size_t)br * FF);
    float4 b0b = *(const float4*)(wr32 + (size_t)br * FF + 4);
    float4 b1a = *(const float4*)(wr32 + (size_t)(br + 16) * FF);
    float4 b1b = *(const float4*)(wr32 + (size_t)(br + 16) * FF + 4);

    for (int ki = 0; ki < NK; ++ki) {
        const int s = ki % NSTAGE;
        *(uint4*)&Bs[s * B_STAGE_H + br * BST + bc8] =
            make_uint4(pack_h2(b0a.x, b0a.y), pack_h2(b0a.z, b0a.w),
                       pack_h2(b0b.x, b0b.y), pack_h2(b0b.z, b0b.w));
        *(uint4*)&Bs[s * B_STAGE_H + (br + 16) * BST + bc8] =
            make_uint4(pack_h2(b1a.x, b1a.y), pack_h2(b1a.z, b1a.w),
                       pack_h2(b1b.x, b1b.y), pack_h2(b1b.z, b1b.w));
        if (ki + 1 < NK) {
            int kt = (ki + 1) * 32;
            b0a = *(const float4*)(wr32 + (size_t)(kt + br) * FF);
            b0b = *(const float4*)(wr32 + (size_t)(kt + br) * FF + 4);
            b1a = *(const float4*)(wr32 + (size_t)(kt + br + 16) * FF);
            b1b = *(const float4*)(wr32 + (size_t)(kt + br + 16) * FF + 4);
        }
        CP_WAIT2();
        __syncthreads();
        int kf = ki + NSTAGE - 1;
        if (kf < NK) {
            int kt = kf * 32;
            uint32_t ao = (kf % NSTAGE) * A_STAGE_H * 2;
            cpa16(a_d0 + ao, xr0 + kt);
            cpa16(a_d1 + ao, xr1 + kt);
        }
        CP_COMMIT();

        const uint32_t asb = as_base + s * A_STAGE_H * 2;
        const uint32_t bsb = bs_base + s * B_STAGE_H * 2;
        #pragma unroll
        for (int ks = 0; ks < 2; ++ks) {
            const int k0 = ks * 16;
            uint32_t af[4][4];
            #pragma unroll
            for (int i = 0; i < 4; ++i) {
                uint32_t ad = asb + ((wm + i * 16 + a_r) * AST + k0 + a_k) * 2;
                ldsm_x4(af[i][0], af[i][1], af[i][2], af[i][3], ad);
            }
            uint32_t bf[4][2];
            #pragma unroll
            for (int jp = 0; jp < 2; ++jp) {
                uint32_t bd = bsb + ((k0 + b_k) * BST + wn + jp * 16 + b_n) * 2;
                ldsm_x4t(bf[jp * 2][0], bf[jp * 2][1],
                         bf[jp * 2 + 1][0], bf[jp * 2 + 1][1], bd);
            }
            #pragma unroll
            for (int i = 0; i < 4; ++i)
                #pragma unroll
                for (int j = 0; j < 4; ++j)
                    mma_f16(acc[i][j][0], acc[i][j][1], acc[i][j][2], acc[i][j][3],
                            af[i][0], af[i][1], af[i][2], af[i][3],
                            bf[j][0], bf[j][1]);
        }
    }

    const float* bp = b1 + (size_t)e * FF + n0;
    #pragma unroll
    for (int j = 0; j < 4; ++j) {
        int col = wn + j * 8 + (lane & 3) * 2;
        float bb0 = bp[col], bb1 = bp[col + 1];
        #pragma unroll
        for (int i = 0; i < 4; ++i) {
            int r0 = row0 + wm + i * 16 + qr;
            float a0 = acc[i][j][0] + bb0, a1 = acc[i][j][1] + bb1;
            uint32_t p0 = pack_h2(a0 / (1.f + __expf(-a0)), a1 / (1.f + __expf(-a1)));
            *(uint32_t*)&g_Hh[(size_t)r0 * FF + n0 + col] = p0;
            float a2 = acc[i][j][2] + bb0, a3 = acc[i][j][3] + bb1;
            uint32_t p1 = pack_h2(a2 / (1.f + __expf(-a2)), a3 / (1.f + __expf(-a3)));
            *(uint32_t*)&g_Hh[(size_t)(r0 + 8) * FF + n0 + col] = p1;
        }
    }
}

__global__ void __launch_bounds__(256, 2) k_mma_gemm2(
    const float* __restrict__ w2, const float* __restrict__ b2,
    float* __restrict__ out)
{
    extern __shared__ __half sm[];
    __half* As = sm;
    __half* Bs = sm + NSTAGE * A_STAGE_H;
    __shared__ int   stok[128];
    __shared__ float ssc[128];

    const int tid = threadIdx.x;
    const int n0 = blockIdx.x * 128;
    const int row0 = blockIdx.y * 128;
    const int e = tile_expert(row0);
    if (e < 0) return;
    const float* __restrict__ w = w2 + (size_t)e * FF * DIM;

    if (tid < 128) { stok[tid] = g_pair_tok[row0 + tid]; ssc[tid] = g_pair_sc[row0 + tid]; }
    __syncthreads();

    const int lane = tid & 31;
    const int wrp = tid >> 5;
    const int wm = (wrp & 1) * 64;
    const int wn = (wrp >> 1) * 32;
    const int qr = lane >> 2;
    const uint32_t as_base = smem_u32(As);
    const uint32_t bs_base = smem_u32(Bs);

    const int ar = tid >> 2;
    const int ac8 = (tid & 3) * 8;
    const __half* hr0 = g_Hh + (size_t)(row0 + ar) * FF + ac8;
    const __half* hr1 = g_Hh + (size_t)(row0 + ar + 64) * FF + ac8;
    const uint32_t a_d0 = as_base + (ar * AST + ac8) * 2;
    const uint32_t a_d1 = as_base + ((ar + 64) * AST + ac8) * 2;

    const int br = tid >> 4;
    const int bc8 = (tid & 15) * 8;
    const float* wr32 = w + n0 + bc8;

    const int a_r = (lane & 15);
    const int a_k = (lane & 16) >> 1;
    const int b_k = (lane & 7) + ((lane & 8) ? 8 : 0);
    const int b_n = (lane & 16) >> 1;

    float acc[4][4][4];
    #pragma unroll
    for (int i = 0; i < 4; i++)
        #pragma unroll
        for (int j = 0; j < 4; j++)
            #pragma unroll
            for (int q = 0; q < 4; q++) acc[i][j][q] = 0.f;

    const int NK = FF / 32;
    #pragma unroll
    for (int s = 0; s < NSTAGE - 1; ++s) {
        int kt = s * 32;
        uint32_t ao = s * A_STAGE_H * 2;
        cpa16(a_d0 + ao, hr0 + kt);
        cpa16(a_d1 + ao, hr1 + kt);
        CP_COMMIT();
    }
    float4 b0a = *(const float4*)(wr32 + (size_t)br * DIM);
    float4 b0b = *(const float4*)(wr32 + (size_t)br * DIM + 4);
    float4 b1a = *(const float4*)(wr32 + (size_t)(br + 16) * DIM);
    float4 b1b = *(const float4*)(wr32 + (size_t)(br + 16) * DIM + 4);

    for (int ki = 0; ki < NK; ++ki) {
        const int s = ki % NSTAGE;
        *(uint4*)&Bs[s * B_STAGE_H + br * BST + bc8] =
            make_uint4(pack_h2(b0a.x, b0a.y), pack_h2(b0a.z, b0a.w),
                       pack_h2(b0b.x, b0b.y), pack_h2(b0b.z, b0b.w));
        *(uint4*)&Bs[s * B_STAGE_H + (br + 16) * BST + bc8] =
            make_uint4(pack_h2(b1a.x, b1a.y), pack_h2(b1a.z, b1a.w),
                       pack_h2(b1b.x, b1b.y), pack_h2(b1b.z, b1b.w));
        if (ki + 1 < NK) {
            int kt = (ki + 1) * 32;
            b0a = *(const float4*)(wr32 + (size_t)(kt + br) * DIM);
            b0b = *(const float4*)(wr32 + (size_t)(kt + br) * DIM + 4);
            b1a = *(const float4*)(wr32 + (size_t)(kt + br + 16) * DIM);
            b1b = *(const float4*)(wr32 + (size_t)(kt + br + 16) * DIM + 4);
        }
        CP_WAIT2();
        __syncthreads();
        int kf = ki + NSTAGE - 1;
        if (kf < NK) {
            int kt = kf * 32;
            uint32_t ao = (kf % NSTAGE) * A_STAGE_H * 2;
            cpa16(a_d0 + ao, hr0 + kt);
            cpa16(a_d1 + ao, hr1 + kt);
        }
        CP_COMMIT();

        const uint32_t asb = as_base + s * A_STAGE_H * 2;
        const uint32_t bsb = bs_base + s * B_STAGE_H * 2;
        #pragma unroll
        for (int ks = 0; ks < 2; ++ks) {
            const int k0 = ks * 16;
            uint32_t af[4][4];
            #pragma unroll
            for (int i = 0; i < 4; ++i) {
                uint32_t ad = asb + ((wm + i * 16 + a_r) * AST + k0 + a_k) * 2;
                ldsm_x4(af[i][0], af[i][1], af[i][2], af[i][3], ad);
            }
            uint32_t bf[4][2];
            #pragma unroll
            for (int jp = 0; jp < 2; ++jp) {
                uint32_t bd = bsb + ((k0 + b_k) * BST + wn + jp * 16 + b_n) * 2;
                ldsm_x4t(bf[jp * 2][0], bf[jp * 2][1],
                         bf[jp * 2 + 1][0], bf[jp * 2 + 1][1], bd);
            }
            #pragma unroll
            for (int i = 0; i < 4; ++i)
                #pragma unroll
                for (int j = 0; j < 4; ++j)
                    mma_f16(acc[i][j][0], acc[i][j][1], acc[i][j][2], acc[i][j][3],
                            af[i][0], af[i][1], af[i][2], af[i][3],
                            bf[j][0], bf[j][1]);
        }
    }

    const float* bp = b2 + (size_t)e * DIM + n0;
    #pragma unroll
    for (int j = 0; j < 4; ++j) {
        int col = wn + j * 8 + (lane & 3) * 2;
        float bb0 = bp[col], bb1 = bp[col + 1];
        #pragma unroll
        for (int i = 0; i < 4; ++i) {
            int m = wm + i * 16 + qr;
            int t0 = stok[m], t1 = stok[m + 8];
            if (t0 >= 0) {
                float s = ssc[m];
                atomicAdd(&out[(size_t)t0 * DIM + n0 + col],     s * (acc[i][j][0] + bb0));
                atomicAdd(&out[(size_t)t0 * DIM + n0 + col + 1], s * (acc[i][j][1] + bb1));
            }
            if (t1 >= 0) {
                float s = ssc[m + 8];
                atomicAdd(&out[(size_t)t1 * DIM + n0 + col],     s * (acc[i][j][2] + bb0));
                atomicAdd(&out[(size_t)t1 * DIM + n0 + col + 1], s * (acc[i][j][3] + bb1));
            }
        }
    }
}

// ---------------- launch -----------------------------------------------------
extern "C" void kernel_launch(void* const* d_in, const int* in_sizes, int n_in,
                              void* d_out, int out_size) {
    const float* x       = (const float*)d_in[0];
    const float* noise   = (const float*)d_in[1];
    const float* gate_w  = (const float*)d_in[2];
    const float* gate_b  = (const float*)d_in[3];
    const float* noise_w = (const float*)d_in[4];
    const float* noise_b = (const float*)d_in[5];
    const float* w1      = (const float*)d_in[6];
    const float* b1      = (const float*)d_in[7];
    const float* w2      = (const float*)d_in[8];
    const float* b2      = (const float*)d_in[9];
    float* out = (float*)d_out;
    (void)in_sizes; (void)n_in;

    static bool init_done = false;
    if (!init_done) {
        cudaFuncSetAttribute(k_mma_gemm1, cudaFuncAttributeMaxDynamicSharedMemorySize, GEMM_SMEM);
        cudaFuncSetAttribute(k_mma_gemm2, cudaFuncAttributeMaxDynamicSharedMemorySize, GEMM_SMEM);
        init_done = true;
    }

    k_setup<<<(T_TOK * DIM / 4 + 255) / 256, 256>>>((float4*)out, gate_w, noise_w);
    k_router<<<T_TOK / 8, 256>>>(x, noise, gate_b, noise_b);
    k_scatter<<<(NPAIR + 255) / 256, 256>>>(out + (out_size - 1));
    k_mma_gemm1<<<dim3(FF / 128, CAPP / 128), 256, GEMM_SMEM>>>(w1, b1);
    k_mma_gemm2<<<dim3(DIM / 128, CAPP / 128), 256, GEMM_SMEM>>>(w2, b2, out);
}

// round 17
// speedup vs baseline: 1.0284x; 1.0183x over previous
#include <cuda_runtime.h>
#include <cuda_fp16.h>
#include <math.h>
#include <stdint.h>

#define T_TOK 4096
#define DIM   1024
#define NE    8
#define FF    4096
#define NPAIR (2*T_TOK)
#define CAPP  9216             // 8192 + 8*128 padding (segments 128-aligned)

// ---------------- scratch (device globals) ----------------------------------
__device__ __half g_Hh[(size_t)CAPP * FF];
__device__ __half g_xh[(size_t)T_TOK * DIM];
__device__ float g_gwc[DIM * NE];          // gate_w + noise_w combined
__device__ int   g_pair_tok[CAPP];
__device__ float g_pair_sc[CAPP];
__device__ int   g_tok_e[NPAIR];
__device__ float g_tok_p[NPAIR];
__device__ int   g_counts[NE];
__device__ int   g_cursor[NE];
__device__ double g_impd[NE];              // summed routing probs (double)

// ---------------- helpers ----------------------------------------------------
__device__ __forceinline__ uint32_t smem_u32(const void* p) {
    return (uint32_t)__cvta_generic_to_shared(p);
}
__device__ __forceinline__ uint32_t pack_h2(float a, float b) {
    __half2 h = __floats2half2_rn(a, b);
    return *(uint32_t*)&h;
}
__device__ __forceinline__ void mma_f16(float& c0, float& c1, float& c2, float& c3,
                                        uint32_t a0, uint32_t a1, uint32_t a2, uint32_t a3,
                                        uint32_t b0, uint32_t b1) {
    asm volatile(
        "mma.sync.aligned.m16n8k16.row.col.f32.f16.f16.f32 "
        "{%0,%1,%2,%3}, {%4,%5,%6,%7}, {%8,%9}, {%0,%1,%2,%3};"
        : "+f"(c0), "+f"(c1), "+f"(c2), "+f"(c3)
        : "r"(a0), "r"(a1), "r"(a2), "r"(a3), "r"(b0), "r"(b1));
}
__device__ __forceinline__ void ldsm_x4(uint32_t& r0, uint32_t& r1, uint32_t& r2,
                                        uint32_t& r3, uint32_t addr) {
    asm volatile("ldmatrix.sync.aligned.m8n8.x4.shared.b16 {%0,%1,%2,%3}, [%4];"
                 : "=r"(r0), "=r"(r1), "=r"(r2), "=r"(r3) : "r"(addr));
}
__device__ __forceinline__ void ldsm_x4t(uint32_t& r0, uint32_t& r1, uint32_t& r2,
                                         uint32_t& r3, uint32_t addr) {
    asm volatile("ldmatrix.sync.aligned.m8n8.x4.trans.shared.b16 {%0,%1,%2,%3}, [%4];"
                 : "=r"(r0), "=r"(r1), "=r"(r2), "=r"(r3) : "r"(addr));
}
__device__ __forceinline__ void cpa16(uint32_t dst, const void* src) {
    asm volatile("cp.async.cg.shared.global [%0], [%1], 16;"
                 :: "r"(dst), "l"(src));
}
#define CP_COMMIT() asm volatile("cp.async.commit_group;" ::: "memory")
#define CP_WAIT2()  asm volatile("cp.async.wait_group 2;"  ::: "memory")

// ---------------- setup kernel ------------------------------------------------
__global__ void k_setup(float4* out, const float* __restrict__ gw,
                        const float* __restrict__ nw) {
    int i = blockIdx.x * blockDim.x + threadIdx.x;
    if (i < T_TOK * DIM / 4) out[i] = make_float4(0.f, 0.f, 0.f, 0.f);
    if (i < CAPP) { g_pair_tok[i] = -1; g_pair_sc[i] = 0.f; }
    if (i < DIM * NE) g_gwc[i] = gw[i] + nw[i];
    if (i < NE) { g_counts[i] = 0; g_cursor[i] = 0; g_impd[i] = 0.0; }
}

// ---------------- router: 8 tokens / 256-thread block ------------------------
__global__ void __launch_bounds__(256) k_router(
    const float* __restrict__ x, const float* __restrict__ noise,
    const float* __restrict__ gb, const float* __restrict__ nb)
{
    __shared__ float sx[8 * DIM];   // 32 KB
    __shared__ float sl[64];
    __shared__ double simp[NE];
    const int tid = threadIdx.x;
    const int t0 = blockIdx.x * 8;

    if (tid < NE) simp[tid] = 0.0;
    for (int i = tid; i < 8 * DIM / 4; i += 256) {
        float4 v = ((const float4*)(x + (size_t)t0 * DIM))[i];
        *(float4*)&sx[i * 4] = v;
    }
    __syncthreads();
    for (int i = tid; i < 8 * DIM / 2; i += 256) {
        *(uint32_t*)&g_xh[(size_t)t0 * DIM + 2 * i] = pack_h2(sx[2 * i], sx[2 * i + 1]);
    }
    const int p = tid >> 2;
    const int q = tid & 3;
    const int tok = p >> 3, e = p & 7;
    const float* xr = &sx[tok * DIM];
    float s = 0.f;
    #pragma unroll 4
    for (int k = q; k < DIM; k += 4)
        s += xr[k] * g_gwc[k * NE + e];
    s += __shfl_down_sync(0xffffffffu, s, 1);
    s += __shfl_down_sync(0xffffffffu, s, 2);
    if (q == 0) sl[p] = s;
    __syncthreads();

    if (tid < 8) {
        int t = t0 + tid;
        float lg[NE];
        #pragma unroll
        for (int k = 0; k < NE; k++)
            lg[k] = sl[tid * NE + k] + gb[k] + nb[k] + noise[t * NE + k];
        float v0 = -1e30f; int i0 = 0;
        #pragma unroll
        for (int k = 0; k < NE; k++) { if (lg[k] > v0) { v0 = lg[k]; i0 = k; } }
        float v1 = -1e30f; int i1 = 0;
        #pragma unroll
        for (int k = 0; k < NE; k++) { if (k == i0) continue; if (lg[k] > v1) { v1 = lg[k]; i1 = k; } }
        float e1 = expf(v1 - v0);
        float z = 1.f + e1;
        float p0 = 1.f / z, p1 = e1 / z;
        g_tok_e[2 * t] = i0;  g_tok_e[2 * t + 1] = i1;
        g_tok_p[2 * t] = p0;  g_tok_p[2 * t + 1] = p1;
        atomicAdd(&g_counts[i0], 1);
        atomicAdd(&g_counts[i1], 1);
        atomicAdd(&simp[i0], (double)p0);
        atomicAdd(&simp[i1], (double)p1);
    }
    __syncthreads();
    if (tid < NE && simp[tid] != 0.0) atomicAdd(&g_impd[tid], simp[tid]);
}

// ---------------- inline segment offsets --------------------------------------
__device__ __forceinline__ int seg_start(int e) {
    int acc = 0;
    #pragma unroll
    for (int i = 0; i < NE; i++)
        if (i < e) acc += ((g_counts[i] + 127) >> 7) << 7;
    return acc;
}
__device__ __forceinline__ int tile_expert(int row0) {
    int acc = 0, e = -1;
    #pragma unroll
    for (int i = 0; i < NE; i++) {
        int pad = ((g_counts[i] + 127) >> 7) << 7;
        if (row0 >= acc && row0 < acc + pad) e = i;
        acc += pad;
    }
    return e;
}

// scatter + (block 0) aux loss
__global__ void k_scatter(float* __restrict__ aux_out) {
    int i = blockIdx.x * blockDim.x + threadIdx.x;
    if (i == 0) {
        float aux = 0.f;
        const float u = 1.f / (float)NE;
        const float logu = logf(u);
        #pragma unroll
        for (int e = 0; e < NE; e++)
            aux += u * (logu - logf((float)(g_impd[e] / (double)T_TOK) + 1e-8f));
        aux_out[0] = aux;
    }
    if (i >= NPAIR) return;
    int t = i >> 1;
    int e = g_tok_e[i];
    float p = g_tok_p[i];
    int pos = seg_start(e) + atomicAdd(&g_cursor[e], 1);
    g_pair_tok[pos] = t;
    g_pair_sc[pos]  = p;
}

// ---------------- SMEM geometry (halfs) --------------------------------------
#define AST 40
#define BST 136
#define A_STAGE_H (128 * AST)
#define B_STAGE_H (32 * BST)
#define NSTAGE 4
#define GEMM_SMEM ((A_STAGE_H + B_STAGE_H) * NSTAGE * 2)   // 75776 B

// =============================================================================
// fp16 mma.sync GEMM, 128x128 CTA tile, 8 warps, K-tile 32 (measured-best R14).
// Grid order: blockIdx.x = row-band (fast), blockIdx.y = n-block, so the two
// co-resident CTAs on an SM share n0 -> identical B LDG streams -> L1 hits.
// A: fp16 via 4-stage cp.async (L1-bypass).  B: fp32 LDG -> fp16 inline.
// =============================================================================

__global__ void __launch_bounds__(256, 2) k_mma_gemm1(
    const float* __restrict__ w1, const float* __restrict__ b1)
{
    extern __shared__ __half sm[];
    __half* As = sm;
    __half* Bs = sm + NSTAGE * A_STAGE_H;
    __shared__ int stok[128];

    const int tid = threadIdx.x;
    const int n0 = blockIdx.y * 128;
    const int row0 = blockIdx.x * 128;
    const int e = tile_expert(row0);
    if (e < 0) return;
    const float* __restrict__ w = w1 + (size_t)e * DIM * FF;

    if (tid < 128) stok[tid] = g_pair_tok[row0 + tid];
    __syncthreads();

    const int lane = tid & 31;
    const int wrp = tid >> 5;
    const int wm = (wrp & 1) * 64;
    const int wn = (wrp >> 1) * 32;
    const int qr = lane >> 2;
    const uint32_t as_base = smem_u32(As);

    const int ar = tid >> 2;
    const int ac8 = (tid & 3) * 8;
    int ta0 = stok[ar];      if (ta0 < 0) ta0 = 0;
    int ta1 = stok[ar + 64]; if (ta1 < 0) ta1 = 0;
    const __half* xr0 = g_xh + (size_t)ta0 * DIM + ac8;
    const __half* xr1 = g_xh + (size_t)ta1 * DIM + ac8;
    const uint32_t a_d0 = as_base + (ar * AST + ac8) * 2;
    const uint32_t a_d1 = as_base + ((ar + 64) * AST + ac8) * 2;

    const int br = tid >> 4;
    const int bc8 = (tid & 15) * 8;
    const float* wr32 = w + n0 + bc8;

    const int a_r = (lane & 15);
    const int a_k = (lane & 16) >> 1;
    const int b_k = (lane & 7) + ((lane & 8) ? 8 : 0);
    const int b_n = (lane & 16) >> 1;
    const uint32_t bs_base = smem_u32(Bs);

    float acc[4][4][4];
    #pragma unroll
    for (int i = 0; i < 4; i++)
        #pragma unroll
        for (int j = 0; j < 4; j++)
            #pragma unroll
            for (int q = 0; q < 4; q++) acc[i][j][q] = 0.f;

    const int NK = DIM / 32;
    #pragma unroll
    for (int s = 0; s < NSTAGE - 1; ++s) {
        int kt = s * 32;
        uint32_t ao = s * A_STAGE_H * 2;
        cpa16(a_d0 + ao, xr0 + kt);
        cpa16(a_d1 + ao, xr1 + kt);
        CP_COMMIT();
    }
    float4 b0a = *(const float4*)(wr32 + (size_t)br * FF);
    float4 b0b = *(const float4*)(wr32 + (size_t)br * FF + 4);
    float4 b1a = *(const float4*)(wr32 + (size_t)(br + 16) * FF);
    float4 b1b = *(const float4*)(wr32 + (size_t)(br + 16) * FF + 4);

    for (int ki = 0; ki < NK; ++ki) {
        const int s = ki % NSTAGE;
        *(uint4*)&Bs[s * B_STAGE_H + br * BST + bc8] =
            make_uint4(pack_h2(b0a.x, b0a.y), pack_h2(b0a.z, b0a.w),
                       pack_h2(b0b.x, b0b.y), pack_h2(b0b.z, b0b.w));
        *(uint4*)&Bs[s * B_STAGE_H + (br + 16) * BST + bc8] =
            make_uint4(pack_h2(b1a.x, b1a.y), pack_h2(b1a.z, b1a.w),
                       pack_h2(b1b.x, b1b.y), pack_h2(b1b.z, b1b.w));
        if (ki + 1 < NK) {
            int kt = (ki + 1) * 32;
            b0a = *(const float4*)(wr32 + (size_t)(kt + br) * FF);
            b0b = *(const float4*)(wr32 + (size_t)(kt + br) * FF + 4);
            b1a = *(const float4*)(wr32 + (size_t)(kt + br + 16) * FF);
            b1b = *(const float4*)(wr32 + (size_t)(kt + br + 16) * FF + 4);
        }
        CP_WAIT2();
        __syncthreads();
        int kf = ki + NSTAGE - 1;
        if (kf < NK) {
            int kt = kf * 32;
            uint32_t ao = (kf % NSTAGE) * A_STAGE_H * 2;
            cpa16(a_d0 + ao, xr0 + kt);
            cpa16(a_d1 + ao, xr1 + kt);
        }
        CP_COMMIT();

        const uint32_t asb = as_base + s * A_STAGE_H * 2;
        const uint32_t bsb = bs_base + s * B_STAGE_H * 2;
        #pragma unroll
        for (int ks = 0; ks < 2; ++ks) {
            const int k0 = ks * 16;
            uint32_t af[4][4];
            #pragma unroll
            for (int i = 0; i < 4; ++i) {
                uint32_t ad = asb + ((wm + i * 16 + a_r) * AST + k0 + a_k) * 2;
                ldsm_x4(af[i][0], af[i][1], af[i][2], af[i][3], ad);
            }
            uint32_t bf[4][2];
            #pragma unroll
            for (int jp = 0; jp < 2; ++jp) {
                uint32_t bd = bsb + ((k0 + b_k) * BST + wn + jp * 16 + b_n) * 2;
                ldsm_x4t(bf[jp * 2][0], bf[jp * 2][1],
                         bf[jp * 2 + 1][0], bf[jp * 2 + 1][1], bd);
            }
            #pragma unroll
            for (int i = 0; i < 4; ++i)
                #pragma unroll
                for (int j = 0; j < 4; ++j)
                    mma_f16(acc[i][j][0], acc[i][j][1], acc[i][j][2], acc[i][j][3],
                            af[i][0], af[i][1], af[i][2], af[i][3],
                            bf[j][0], bf[j][1]);
        }
    }

    const float* bp = b1 + (size_t)e * FF + n0;
    #pragma unroll
    for (int j = 0; j < 4; ++j) {
        int col = wn + j * 8 + (lane & 3) * 2;
        float bb0 = bp[col], bb1 = bp[col + 1];
        #pragma unroll
        for (int i = 0; i < 4; ++i) {
            int r0 = row0 + wm + i * 16 + qr;
            float a0 = acc[i][j][0] + bb0, a1 = acc[i][j][1] + bb1;
            uint32_t p0 = pack_h2(a0 / (1.f + __expf(-a0)), a1 / (1.f + __expf(-a1)));
            *(uint32_t*)&g_Hh[(size_t)r0 * FF + n0 + col] = p0;
            float a2 = acc[i][j][2] + bb0, a3 = acc[i][j][3] + bb1;
            uint32_t p1 = pack_h2(a2 / (1.f + __expf(-a2)), a3 / (1.f + __expf(-a3)));
            *(uint32_t*)&g_Hh[(size_t)(r0 + 8) * FF + n0 + col] = p1;
        }
    }
}

__global__ void __launch_bounds__(256, 2) k_mma_gemm2(
    const float* __restrict__ w2, const float* __restrict__ b2,
    float* __restrict__ out)
{
    extern __shared__ __half sm[];
    __half* As = sm;
    __half* Bs = sm + NSTAGE * A_STAGE_H;
    __shared__ int   stok[128];
    __shared__ float ssc[128];

    const int tid = threadIdx.x;
    const int n0 = blockIdx.y * 128;
    const int row0 = blockIdx.x * 128;
    const int e = tile_expert(row0);
    if (e < 0) return;
    const float* __restrict__ w = w2 + (size_t)e * FF * DIM;

    if (tid < 128) { stok[tid] = g_pair_tok[row0 + tid]; ssc[tid] = g_pair_sc[row0 + tid]; }
    __syncthreads();

    const int lane = tid & 31;
    const int wrp = tid >> 5;
    const int wm = (wrp & 1) * 64;
    const int wn = (wrp >> 1) * 32;
    const int qr = lane >> 2;
    const uint32_t as_base = smem_u32(As);
    const uint32_t bs_base = smem_u32(Bs);

    const int ar = tid >> 2;
    const int ac8 = (tid & 3) * 8;
    const __half* hr0 = g_Hh + (size_t)(row0 + ar) * FF + ac8;
    const __half* hr1 = g_Hh + (size_t)(row0 + ar + 64) * FF + ac8;
    const uint32_t a_d0 = as_base + (ar * AST + ac8) * 2;
    const uint32_t a_d1 = as_base + ((ar + 64) * AST + ac8) * 2;

    const int br = tid >> 4;
    const int bc8 = (tid & 15) * 8;
    const float* wr32 = w + n0 + bc8;

    const int a_r = (lane & 15);
    const int a_k = (lane & 16) >> 1;
    const int b_k = (lane & 7) + ((lane & 8) ? 8 : 0);
    const int b_n = (lane & 16) >> 1;

    float acc[4][4][4];
    #pragma unroll
    for (int i = 0; i < 4; i++)
        #pragma unroll
        for (int j = 0; j < 4; j++)
            #pragma unroll
            for (int q = 0; q < 4; q++) acc[i][j][q] = 0.f;

    const int NK = FF / 32;
    #pragma unroll
    for (int s = 0; s < NSTAGE - 1; ++s) {
        int kt = s * 32;
        uint32_t ao = s * A_STAGE_H * 2;
        cpa16(a_d0 + ao, hr0 + kt);
        cpa16(a_d1 + ao, hr1 + kt);
        CP_COMMIT();
    }
    float4 b0a = *(const float4*)(wr32 + (size_t)br * DIM);
    float4 b0b = *(const float4*)(wr32 + (size_t)br * DIM + 4);
    float4 b1a = *(const float4*)(wr32 + (size_t)(br + 16) * DIM);
    float4 b1b = *(const float4*)(wr32 + (size_t)(br + 16) * DIM + 4);

    for (int ki = 0; ki < NK; ++ki) {
        const int s = ki % NSTAGE;
        *(uint4*)&Bs[s * B_STAGE_H + br * BST + bc8] =
            make_uint4(pack_h2(b0a.x, b0a.y), pack_h2(b0a.z, b0a.w),
                       pack_h2(b0b.x, b0b.y), pack_h2(b0b.z, b0b.w));
        *(uint4*)&Bs[s * B_STAGE_H + (br + 16) * BST + bc8] =
            make_uint4(pack_h2(b1a.x, b1a.y), pack_h2(b1a.z, b1a.w),
                       pack_h2(b1b.x, b1b.y), pack_h2(b1b.z, b1b.w));
        if (ki + 1 < NK) {
            int kt = (ki + 1) * 32;
            b0a = *(const float4*)(wr32 + (size_t)(kt + br) * DIM);
            b0b = *(const float4*)(wr32 + (size_t)(kt + br) * DIM + 4);
            b1a = *(const float4*)(wr32 + (size_t)(kt + br + 16) * DIM);
            b1b = *(const float4*)(wr32 + (size_t)(kt + br + 16) * DIM + 4);
        }
        CP_WAIT2();
        __syncthreads();
        int kf = ki + NSTAGE - 1;
        if (kf < NK) {
            int kt = kf * 32;
            uint32_t ao = (kf % NSTAGE) * A_STAGE_H * 2;
            cpa16(a_d0 + ao, hr0 + kt);
            cpa16(a_d1 + ao, hr1 + kt);
        }
        CP_COMMIT();

        const uint32_t asb = as_base + s * A_STAGE_H * 2;
        const uint32_t bsb = bs_base + s * B_STAGE_H * 2;
        #pragma unroll
        for (int ks = 0; ks < 2; ++ks) {
            const int k0 = ks * 16;
            uint32_t af[4][4];
            #pragma unroll
            for (int i = 0; i < 4; ++i) {
                uint32_t ad = asb + ((wm + i * 16 + a_r) * AST + k0 + a_k) * 2;
                ldsm_x4(af[i][0], af[i][1], af[i][2], af[i][3], ad);
            }
            uint32_t bf[4][2];
            #pragma unroll
            for (int jp = 0; jp < 2; ++jp) {
                uint32_t bd = bsb + ((k0 + b_k) * BST + wn + jp * 16 + b_n) * 2;
                ldsm_x4t(bf[jp * 2][0], bf[jp * 2][1],
                         bf[jp * 2 + 1][0], bf[jp * 2 + 1][1], bd);
            }
            #pragma unroll
            for (int i = 0; i < 4; ++i)
                #pragma unroll
                for (int j = 0; j < 4; ++j)
                    mma_f16(acc[i][j][0], acc[i][j][1], acc[i][j][2], acc[i][j][3],
                            af[i][0], af[i][1], af[i][2], af[i][3],
                            bf[j][0], bf[j][1]);
        }
    }

    const float* bp = b2 + (size_t)e * DIM + n0;
    #pragma unroll
    for (int j = 0; j < 4; ++j) {
        int col = wn + j * 8 + (lane & 3) * 2;
        float bb0 = bp[col], bb1 = bp[col + 1];
        #pragma unroll
        for (int i = 0; i < 4; ++i) {
            int m = wm + i * 16 + qr;
            int t0 = stok[m], t1 = stok[m + 8];
            if (t0 >= 0) {
                float s = ssc[m];
                atomicAdd(&out[(size_t)t0 * DIM + n0 + col],     s * (acc[i][j][0] + bb0));
                atomicAdd(&out[(size_t)t0 * DIM + n0 + col + 1], s * (acc[i][j][1] + bb1));
            }
            if (t1 >= 0) {
                float s = ssc[m + 8];
                atomicAdd(&out[(size_t)t1 * DIM + n0 + col],     s * (acc[i][j][2] + bb0));
                atomicAdd(&out[(size_t)t1 * DIM + n0 + col + 1], s * (acc[i][j][3] + bb1));
            }
        }
    }
}

// ---------------- launch -----------------------------------------------------
extern "C" void kernel_launch(void* const* d_in, const int* in_sizes, int n_in,
                              void* d_out, int out_size) {
    const float* x       = (const float*)d_in[0];
    const float* noise   = (const float*)d_in[1];
    const float* gate_w  = (const float*)d_in[2];
    const float* gate_b  = (const float*)d_in[3];
    const float* noise_w = (const float*)d_in[4];
    const float* noise_b = (const float*)d_in[5];
    const float* w1      = (const float*)d_in[6];
    const float* b1      = (const float*)d_in[7];
    const float* w2      = (const float*)d_in[8];
    const float* b2      = (const float*)d_in[9];
    float* out = (float*)d_out;
    (void)in_sizes; (void)n_in;

    static bool init_done = false;
    if (!init_done) {
        cudaFuncSetAttribute(k_mma_gemm1, cudaFuncAttributeMaxDynamicSharedMemorySize, GEMM_SMEM);
        cudaFuncSetAttribute(k_mma_gemm2, cudaFuncAttributeMaxDynamicSharedMemorySize, GEMM_SMEM);
        init_done = true;
    }

    k_setup<<<(T_TOK * DIM / 4 + 255) / 256, 256>>>((float4*)out, gate_w, noise_w);
    k_router<<<T_TOK / 8, 256>>>(x, noise, gate_b, noise_b);
    k_scatter<<<(NPAIR + 255) / 256, 256>>>(out + (out_size - 1));
    // grid: x = row-band (fast-varying), y = n-block -> co-resident CTAs share B
    k_mma_gemm1<<<dim3(CAPP / 128, FF / 128), 256, GEMM_SMEM>>>(w1, b1);
    k_mma_gemm2<<<dim3(CAPP / 128, DIM / 128), 256, GEMM_SMEM>>>(w2, b2, out);
}